// round 11
// baseline (speedup 1.0000x reference)
#include <cuda_runtime.h>

// Lorenz96 to T=1.0, F=8 — classic RK4, dt=1/16, 16 steps (dt ladder final:
// measured rel_err 7.05e-4 vs 1e-3; 14 steps would fail per calibrated law).
// NEW vs r10: 4 lanes/row x 10 elems/lane (was 2x20). Per-element arithmetic
// is identical (bit-exact rel_err), fma warp-instruction count conserved, but
// live state halves (30 floats -> ~46 regs) => occupancy ~28->~44 warps/SM,
// hiding the latency that left 17% of fma-pipe cycles idle in r10.
// Halos via width-4 shfl: left lane's elems 8,9 and right lane's elem 0.

#define L96_DIM   40
#define L96_EPL   10
#define L96_STEPS 16
#define L96_DT    0.0625f

// In-place RHS: v = f(v) = (v[i+1]-v[i-2])*v[i-1] - v[i] + F, cyclic over the
// 4-lane group (width-4 shuffles; srcLane is taken mod width).
__device__ __forceinline__ void l96_rhs_ip(float v[L96_EPL], int sub) {
    const unsigned m = 0xffffffffu;
    float h8 = __shfl_sync(m, v[8], sub + 3, 4);   // x[i0-2]
    float h9 = __shfl_sync(m, v[9], sub + 3, 4);   // x[i0-1]
    float h0 = __shfl_sync(m, v[0], sub + 1, 4);   // x[i0+10]
    float om2 = h8, om1 = h9;
    #pragma unroll
    for (int i = 0; i < L96_EPL; i++) {
        float cur = v[i];
        float nxt = (i < L96_EPL - 1) ? v[i + 1] : h0;
        v[i] = fmaf(nxt - om2, om1, 8.0f - cur);
        om2 = om1; om1 = cur;
    }
}

__global__ void __launch_bounds__(128)
lorenz96_kernel(const float* __restrict__ x_in, float* __restrict__ x_out, int batch) {
    int tid = blockIdx.x * blockDim.x + threadIdx.x;
    int row = tid >> 2;        // 4 lanes per row
    if (row >= batch) return;
    int sub = tid & 3;

    const unsigned m = 0xffffffffu;
    const float DT  = L96_DT;
    const float DTH = 0.5f * DT;     // dt/2
    const float DT6 = DT / 6.0f;     // dt/6

    const float2* xp2 = (const float2*)(x_in  + (size_t)row * L96_DIM + sub * L96_EPL);
    float2*       op2 = (float2*)      (x_out + (size_t)row * L96_DIM + sub * L96_EPL);

    float X[L96_EPL], S[L96_EPL], Y[L96_EPL];
    #pragma unroll
    for (int j = 0; j < 5; j++) {
        float2 v = xp2[j];
        X[2*j] = v.x; X[2*j+1] = v.y;
    }

    #pragma unroll 1
    for (int step = 0; step < L96_STEPS; step++) {
        // ---- stage 1: k1 = f(x) -> S; y = x + dt/2*k1 ----
        {
            float h8 = __shfl_sync(m, X[8], sub + 3, 4);
            float h9 = __shfl_sync(m, X[9], sub + 3, 4);
            float h0 = __shfl_sync(m, X[0], sub + 1, 4);
            float om2 = h8, om1 = h9;
            #pragma unroll
            for (int i = 0; i < L96_EPL; i++) {
                float cur = X[i];
                float nxt = (i < L96_EPL - 1) ? X[i + 1] : h0;
                S[i] = fmaf(nxt - om2, om1, 8.0f - cur);   // S = k1
                om2 = om1; om1 = cur;
            }
        }
        #pragma unroll
        for (int i = 0; i < L96_EPL; i++) Y[i] = fmaf(DTH, S[i], X[i]);

        // ---- stage 2: k2 = f(y); s += 2*k2; y = x + dt/2*k2 ----
        l96_rhs_ip(Y, sub);
        #pragma unroll
        for (int i = 0; i < L96_EPL; i++) {
            float k2 = Y[i];
            S[i] = fmaf(2.0f, k2, S[i]);
            Y[i] = fmaf(DTH, k2, X[i]);
        }

        // ---- stage 3: k3 = f(y); s += 2*k3; y = x + dt*k3 ----
        l96_rhs_ip(Y, sub);
        #pragma unroll
        for (int i = 0; i < L96_EPL; i++) {
            float k3 = Y[i];
            S[i] = fmaf(2.0f, k3, S[i]);
            Y[i] = fmaf(DT, k3, X[i]);
        }

        // ---- stage 4: k4 = f(y); x += dt/6*(s + k4) ----
        l96_rhs_ip(Y, sub);
        #pragma unroll
        for (int i = 0; i < L96_EPL; i++)
            X[i] = fmaf(DT6, S[i] + Y[i], X[i]);
    }

    #pragma unroll
    for (int j = 0; j < 5; j++) {
        float2 v;
        v.x = X[2*j]; v.y = X[2*j+1];
        op2[j] = v;
    }
}

extern "C" void kernel_launch(void* const* d_in, const int* in_sizes, int n_in,
                              void* d_out, int out_size) {
    const float* x = (const float*)d_in[0];
    float* out = (float*)d_out;
    int batch = in_sizes[0] / L96_DIM;       // 262144
    int total_threads = batch * 4;           // 4 lanes per row
    int block = 128;
    int grid = (total_threads + block - 1) / block;
    lorenz96_kernel<<<grid, block>>>(x, out, batch);
}